// round 14
// baseline (speedup 1.0000x reference)
#include <cuda_runtime.h>
#include <float.h>

// Density_loss: per-cloud x-sort (u64 bitonic, warp-local tail substeps), then
// sorted-order kNN with sentinel pads, bitonic-network fill, and split-chain
// (two independent 8-chains) top-16 inserts. B=8, N=2048, C=3, K=16.

#define NPTS   2048
#define BATCH  8
#define CLOUDS (2 * BATCH)     // 16
#define KNN    16
#define QBLK   256
#define BLK    256
#define TILES  (NPTS / QBLK)   // 8
#define WINP   64              // phase-A half-window (pairs)
#define CHUNK  32
#define PAD    2080
#define FULLM  0xffffffffu

__device__ float4 g_sorted[CLOUDS * NPTS];
__device__ float  g_partials[CLOUDS * TILES];

// ---------------------------------------------------------------------------
// Kernel 1: per-cloud bitonic sort by x (key|idx packed u64).
// Substeps with j<=16 act entirely inside a warp-owned 64-element span:
// thread t (warp w) touches only elements [64w, 64w+64) -> __syncwarp only.
// ---------------------------------------------------------------------------
__global__ __launch_bounds__(1024, 1)
void sort_kernel(const float* __restrict__ seed,
                 const float* __restrict__ gt) {
    __shared__ unsigned long long a[NPTS];

    const int cloud = blockIdx.x;
    const float* __restrict__ pts =
        ((cloud >> 3) == 0 ? seed : gt) + (size_t)(cloud & 7) * NPTS * 3;

    for (int i = threadIdx.x; i < NPTS; i += 1024) {
        const unsigned bits = __float_as_uint(pts[3 * i]);
        const unsigned mono =
            (bits & 0x80000000u) ? ~bits : (bits | 0x80000000u);
        a[i] = ((unsigned long long)mono << 32) | (unsigned)i;
    }
    __syncthreads();

    const int t = threadIdx.x;             // NPTS/2 CE workers
    for (int k = 2; k <= NPTS; k <<= 1) {
        int j = k >> 1;
        // Cross-warp substeps: full barrier.
        for (; j >= 32; j >>= 1) {
            const int i = ((t & ~(j - 1)) << 1) | (t & (j - 1));
            const int p = i | j;
            const bool up = ((i & k) == 0);
            const unsigned long long A = a[i], B = a[p];
            if ((A > B) == up) { a[i] = B; a[p] = A; }
            __syncthreads();
        }
        // Warp-local substeps (j <= 16).
        for (; j > 0; j >>= 1) {
            const int i = ((t & ~(j - 1)) << 1) | (t & (j - 1));
            const int p = i | j;
            const bool up = ((i & k) == 0);
            const unsigned long long A = a[i], B = a[p];
            if ((A > B) == up) { a[i] = B; a[p] = A; }
            __syncwarp();
        }
        if (k >= 32) __syncthreads();      // next stage crosses warps
    }

    for (int i = threadIdx.x; i < NPTS; i += 1024) {
        const int id = (int)(a[i] & 0xFFFFFFFFu);
        const float x = pts[3 * id + 0];
        const float y = pts[3 * id + 1];
        const float z = pts[3 * id + 2];
        g_sorted[cloud * NPTS + i] =
            make_float4(-2.0f * x, -2.0f * y, -2.0f * z,
                        fmaf(x, x, fmaf(y, y, z * z)));
    }
}

// ---------------------------------------------------------------------------
// Kernel 2: kNN — sentinel-padded sorted scan, network fill, split-chain.
// ---------------------------------------------------------------------------
extern __shared__ float4 dyn_smem[];

__global__ __launch_bounds__(BLK, 1)
void knn_kernel() {
    float4* const sp = dyn_smem + PAD;
    __shared__ float sred[BLK / 32];

    const int tile  = blockIdx.x;
    const int b     = blockIdx.y;
    const int which = blockIdx.z;
    const int cloud = which * BATCH + b;

    const float4* __restrict__ src = g_sorted + cloud * NPTS;
    for (int i = threadIdx.x; i < NPTS; i += BLK) sp[i] = src[i];
    const float4 sent = make_float4(-2e19f, 0.0f, 0.0f, 1e38f);
    for (int i = threadIdx.x; i < PAD; i += BLK) {
        dyn_smem[i]              = sent;
        dyn_smem[PAD + NPTS + i] = sent;
    }
    __syncthreads();

    const int lane  = threadIdx.x & 31;
    const int qrank = tile * QBLK + threadIdx.x;
    const float4 q  = sp[qrank];
    const float Qx  = -0.5f * q.x;
    const float cx  = Qx;
    const float cy  = -0.5f * q.y;
    const float cz  = -0.5f * q.z;
    const float Qs  = q.w;

    auto dist = [&](const float4 p) -> float {
        return fmaf(p.x, cx, fmaf(p.y, cy, fmaf(p.z, cz, Qs + p.w)));
    };

    // ---- Phase 0: fill via 16-element bitonic network (ranks q-8..q+7) ----
    float best[KNN];
#pragma unroll
    for (int u = 0; u < KNN; ++u) best[u] = dist(sp[qrank - 8 + u]);
#pragma unroll
    for (int k = 2; k <= 16; k <<= 1) {
#pragma unroll
        for (int j = k >> 1; j > 0; j >>= 1) {
#pragma unroll
            for (int i = 0; i < 16; ++i) {
                const int p = i ^ j;
                if (p > i) {
                    const bool up = ((i & k) == 0);   // k=16: always true
                    const float lo = fminf(best[i], best[p]);
                    const float hi = fmaxf(best[i], best[p]);
                    best[i] = up ? lo : hi;
                    best[p] = up ? hi : lo;
                }
            }
        }
    }
    float thresh = best[KNN - 1];

    // Split-chain insert: two INDEPENDENT 8-chains -> half the serial depth.
    auto insert1 = [&](float v) {
        const float lo = fminf(v, best[7]);
        const float up = fmaxf(v, best[7]);
        float a = lo;
#pragma unroll
        for (int k = 0; k < 8; ++k) {
            const float t = fminf(best[k], a);
            a       = fmaxf(best[k], a);
            best[k] = t;
        }
        float c = up;
#pragma unroll
        for (int k = 8; k < 16; ++k) {
            const float t = fminf(best[k], c);
            c       = fmaxf(best[k], c);
            best[k] = t;
        }
    };
    auto pair_insert = [&](float d0, float d1) {
        if (__any_sync(FULLM, fminf(d0, d1) < thresh)) {
            insert1((d0 < thresh) ? d0 : FLT_MAX);
            insert1((d1 < thresh) ? d1 : FLT_MAX);
            thresh = best[KNN - 1];
        }
    };

    // ---- Phase A: regular symmetric window, ranks (q-WINP..q-9, q+8..q+WINP-1)
#pragma unroll 2
    for (int off = 8; off < WINP; ++off) {
        const float4 pr = sp[qrank + off];
        const float4 pl = sp[qrank - 1 - off];
        pair_insert(dist(pl), dist(pr));
    }

    // ---- Phase B: extend left, chunked prune ----
    for (int off = WINP; off < NPTS; off += CHUNK) {
        const float xn = -0.5f * sp[qrank - 1 - off].x;
        const float dx = Qx - xn;
        if (__all_sync(FULLM, dx * dx >= thresh)) break;
#pragma unroll
        for (int u = 0; u < CHUNK; u += 2) {
            const float4 p0 = sp[qrank - 1 - off - u];
            const float4 p1 = sp[qrank - 2 - off - u];
            pair_insert(dist(p0), dist(p1));
        }
    }

    // ---- Phase C: extend right, chunked prune ----
    for (int off = WINP; off < NPTS; off += CHUNK) {
        const float xn = -0.5f * sp[qrank + off].x;
        const float dx = xn - Qx;
        if (__all_sync(FULLM, dx * dx >= thresh)) break;
#pragma unroll
        for (int u = 0; u < CHUNK; u += 2) {
            const float4 p0 = sp[qrank + off + u];
            const float4 p1 = sp[qrank + off + u + 1];
            pair_insert(dist(p0), dist(p1));
        }
    }

    // ---- Mean of 16 NN, deterministic block reduction ----
    float s = 0.0f;
#pragma unroll
    for (int k = 0; k < KNN; ++k) s += best[k];
    s *= (1.0f / KNN);

#pragma unroll
    for (int o = 16; o > 0; o >>= 1)
        s += __shfl_down_sync(FULLM, s, o);
    if (lane == 0) sred[threadIdx.x >> 5] = s;
    __syncthreads();
    if (threadIdx.x == 0) {
        float t = 0.0f;
#pragma unroll
        for (int w = 0; w < BLK / 32; ++w) t += sred[w];
        g_partials[cloud * TILES + tile] = t;
    }
}

// ---------------------------------------------------------------------------
// Kernel 3: finalize MSE.
// ---------------------------------------------------------------------------
__global__ void finalize_kernel(float* __restrict__ out) {
    const int lane = threadIdx.x;   // 32 threads
    float s = 0.0f;
    if (lane < CLOUDS) {
        const int base = lane * TILES;
#pragma unroll
        for (int t = 0; t < TILES; ++t) s += g_partials[base + t];
        s *= (1.0f / NPTS);
    }
    const float other = __shfl_xor_sync(FULLM, s, 8);
    const float diff = s - other;
    float d2 = diff * diff;
    if (lane >= 8) d2 = 0.0f;
#pragma unroll
    for (int o = 4; o > 0; o >>= 1)
        d2 += __shfl_down_sync(FULLM, d2, o);
    if (lane == 0) out[0] = d2 * (1.0f / BATCH);
}

extern "C" void kernel_launch(void* const* d_in, const int* in_sizes, int n_in,
                              void* d_out, int out_size) {
    const float* seed = (const float*)d_in[0];
    const float* gt_s = (const float*)d_in[1];
    float* out = (float*)d_out;

    const size_t dyn_bytes = (size_t)(2 * PAD + NPTS) * sizeof(float4);
    cudaFuncSetAttribute(knn_kernel,
                         cudaFuncAttributeMaxDynamicSharedMemorySize,
                         (int)dyn_bytes);

    sort_kernel<<<CLOUDS, 1024>>>(seed, gt_s);
    dim3 grid(TILES, BATCH, 2);
    knn_kernel<<<grid, BLK, dyn_bytes>>>();
    finalize_kernel<<<1, 32>>>(out);
}

// round 15
// speedup vs baseline: 1.2034x; 1.2034x over previous
#include <cuda_runtime.h>
#include <float.h>

// Density_loss: per-cloud x-sort (u64 bitonic), then sorted-order kNN with
// sentinel pads, paired votes, and WARP-TILE TRANSPOSE load balancing
// (each CTA gets a stratified mix of central/tail warps). Finalize fused via
// last-CTA threadfence reduction. B=8, N=2048, C=3, K=16.

#define NPTS   2048
#define BATCH  8
#define CLOUDS (2 * BATCH)     // 16
#define KNN    16
#define BLK    256
#define TILES  (NPTS / BLK)    // 8 CTAs per cloud
#define NCTAS  (CLOUDS * TILES) // 128 total
#define WINP   16              // phase-A half-window (pairs, incl. fill)
#define CHUNK  16              // per-side candidates per prune step
#define PAD    2080
#define FULLM  0xffffffffu

__device__ float4   g_sorted[CLOUDS * NPTS];
__device__ float    g_partials[NCTAS];
__device__ unsigned g_done = 0;        // last-CTA counter (self-resetting)

// ---------------------------------------------------------------------------
// Kernel 1: per-cloud bitonic sort by x (key|idx packed u64). R13-proven form.
// ---------------------------------------------------------------------------
__global__ __launch_bounds__(1024, 1)
void sort_kernel(const float* __restrict__ seed,
                 const float* __restrict__ gt) {
    __shared__ unsigned long long a[NPTS];

    const int cloud = blockIdx.x;
    const float* __restrict__ pts =
        ((cloud >> 3) == 0 ? seed : gt) + (size_t)(cloud & 7) * NPTS * 3;

    for (int i = threadIdx.x; i < NPTS; i += 1024) {
        const unsigned bits = __float_as_uint(pts[3 * i]);
        const unsigned mono =
            (bits & 0x80000000u) ? ~bits : (bits | 0x80000000u);
        a[i] = ((unsigned long long)mono << 32) | (unsigned)i;
    }
    __syncthreads();

    const int t = threadIdx.x;             // exactly NPTS/2 CE workers
    for (int k = 2; k <= NPTS; k <<= 1) {
        for (int j = k >> 1; j > 0; j >>= 1) {
            const int i = ((t & ~(j - 1)) << 1) | (t & (j - 1));
            const int p = i | j;
            const bool up = ((i & k) == 0);
            const unsigned long long A = a[i], B = a[p];
            if ((A > B) == up) { a[i] = B; a[p] = A; }
            __syncthreads();
        }
    }

    for (int i = threadIdx.x; i < NPTS; i += 1024) {
        const int id = (int)(a[i] & 0xFFFFFFFFu);
        const float x = pts[3 * id + 0];
        const float y = pts[3 * id + 1];
        const float z = pts[3 * id + 2];
        g_sorted[cloud * NPTS + i] =
            make_float4(-2.0f * x, -2.0f * y, -2.0f * z,
                        fmaf(x, x, fmaf(y, y, z * z)));
    }
}

// ---------------------------------------------------------------------------
// Kernel 2: kNN — transposed warp assignment + sentinel scan + fused finalize.
// ---------------------------------------------------------------------------
extern __shared__ float4 dyn_smem[];

__global__ __launch_bounds__(BLK, 1)
void knn_kernel(float* __restrict__ out) {
    float4* const sp = dyn_smem + PAD;
    __shared__ float sred[BLK / 32];

    const int cta   = blockIdx.x;          // slot within this cloud (0..7)
    const int b     = blockIdx.y;
    const int which = blockIdx.z;
    const int cloud = which * BATCH + b;

    const float4* __restrict__ src = g_sorted + cloud * NPTS;
    for (int i = threadIdx.x; i < NPTS; i += BLK) sp[i] = src[i];
    const float4 sent = make_float4(-2e19f, 0.0f, 0.0f, 1e38f);
    for (int i = threadIdx.x; i < PAD; i += BLK) {
        dyn_smem[i]              = sent;   // left pad
        dyn_smem[PAD + NPTS + i] = sent;   // right pad
    }
    __syncthreads();

    const int lane = threadIdx.x & 31;
    const int w    = threadIdx.x >> 5;     // warp within CTA (0..7)
    // Warp-tile transpose: warp block index = w*TILES + cta (stratified mix
    // of central/tail rank regions per CTA). Lanes stay rank-consecutive.
    const int qrank = (w * TILES + cta) * 32 + lane;

    const float4 q  = sp[qrank];
    const float Qx  = -0.5f * q.x;         // true x of query
    const float cx  = Qx;
    const float cy  = -0.5f * q.y;
    const float cz  = -0.5f * q.z;
    const float Qs  = q.w;

    float best[KNN];
#pragma unroll
    for (int k = 0; k < KNN; ++k) best[k] = FLT_MAX;
    float thresh = FLT_MAX;

    auto dist = [&](const float4 p) -> float {
        return fmaf(p.x, cx, fmaf(p.y, cy, fmaf(p.z, cz, Qs + p.w)));
    };
    auto pair_insert = [&](float d0, float d1) {
        if (__any_sync(FULLM, fminf(d0, d1) < thresh)) {
            float v = (d0 < thresh) ? d0 : FLT_MAX;
#pragma unroll
            for (int k = 0; k < KNN; ++k) {
                const float lo = fminf(best[k], v);
                v       = fmaxf(best[k], v);
                best[k] = lo;
            }
            float u = (d1 < thresh) ? d1 : FLT_MAX;
#pragma unroll
            for (int k = 0; k < KNN; ++k) {
                const float lo = fminf(best[k], u);
                u       = fmaxf(best[k], u);
                best[k] = lo;
            }
            thresh = best[KNN - 1];
        }
    };

    // ---- Phase A: regular symmetric window, ranks [q-WINP, q+WINP-1] ----
#pragma unroll 2
    for (int off = 0; off < WINP; ++off) {
        const float4 pr = sp[qrank + off];       // off=0 -> self (d ~ 0)
        const float4 pl = sp[qrank - 1 - off];
        pair_insert(dist(pl), dist(pr));
    }

    // ---- Phase B: extend left, chunked, frontier prune vote ----
    for (int off = WINP; off < NPTS; off += CHUNK) {
        const float xn = -0.5f * sp[qrank - 1 - off].x;
        const float dx = Qx - xn;
        if (__all_sync(FULLM, dx * dx >= thresh)) break;
#pragma unroll
        for (int u = 0; u < CHUNK; u += 2) {
            const float4 p0 = sp[qrank - 1 - off - u];
            const float4 p1 = sp[qrank - 2 - off - u];
            pair_insert(dist(p0), dist(p1));
        }
    }

    // ---- Phase C: extend right, chunked, frontier prune vote ----
    for (int off = WINP; off < NPTS; off += CHUNK) {
        const float xn = -0.5f * sp[qrank + off].x;
        const float dx = xn - Qx;
        if (__all_sync(FULLM, dx * dx >= thresh)) break;
#pragma unroll
        for (int u = 0; u < CHUNK; u += 2) {
            const float4 p0 = sp[qrank + off + u];
            const float4 p1 = sp[qrank + off + u + 1];
            pair_insert(dist(p0), dist(p1));
        }
    }

    // ---- Mean of 16 NN, deterministic block reduction ----
    float s = 0.0f;
#pragma unroll
    for (int k = 0; k < KNN; ++k) s += best[k];
    s *= (1.0f / KNN);

#pragma unroll
    for (int o = 16; o > 0; o >>= 1)
        s += __shfl_down_sync(FULLM, s, o);
    if (lane == 0) sred[w] = s;
    __syncthreads();

    __shared__ bool s_last;
    if (threadIdx.x == 0) {
        float t = 0.0f;
#pragma unroll
        for (int ww = 0; ww < BLK / 32; ++ww) t += sred[ww];
        g_partials[cloud * TILES + cta] = t;
        __threadfence();
        const unsigned prev = atomicAdd(&g_done, 1u);
        s_last = (prev == NCTAS - 1);
    }
    __syncthreads();

    // ---- Fused finalize: last CTA computes the MSE (warp 0 only) ----
    if (s_last && threadIdx.x < 32) {
        __threadfence();
        if (threadIdx.x == 0) g_done = 0;       // reset for next replay
        float acc = 0.0f;
        if (lane < CLOUDS) {
            const int base = lane * TILES;       // lane = which*8 + b
#pragma unroll
            for (int t = 0; t < TILES; ++t) acc += g_partials[base + t];
            acc *= (1.0f / NPTS);
        }
        const float other = __shfl_xor_sync(FULLM, acc, 8);  // seed <-> gt
        const float diff  = acc - other;
        float d2 = diff * diff;
        if (lane >= 8) d2 = 0.0f;
#pragma unroll
        for (int o = 4; o > 0; o >>= 1)
            d2 += __shfl_down_sync(FULLM, d2, o);
        if (lane == 0) out[0] = d2 * (1.0f / BATCH);
    }
}

extern "C" void kernel_launch(void* const* d_in, const int* in_sizes, int n_in,
                              void* d_out, int out_size) {
    const float* seed = (const float*)d_in[0];
    const float* gt_s = (const float*)d_in[1];
    float* out = (float*)d_out;

    const size_t dyn_bytes = (size_t)(2 * PAD + NPTS) * sizeof(float4);
    cudaFuncSetAttribute(knn_kernel,
                         cudaFuncAttributeMaxDynamicSharedMemorySize,
                         (int)dyn_bytes);

    sort_kernel<<<CLOUDS, 1024>>>(seed, gt_s);
    dim3 grid(TILES, BATCH, 2);
    knn_kernel<<<grid, BLK, dyn_bytes>>>(out);
}